// round 3
// baseline (speedup 1.0000x reference)
#include <cuda_runtime.h>
#include <cuda_bf16.h>

// Problem constants
#define TT   64
#define WW   88
#define HPc  48
#define CIN  53
#define HLc  12
#define G4   48
#define NHh  4
#define HDd  6
#define NUc  24
#define KK   25
#define NPX  (TT*WW)   // 5632
#define PITCH 26       // even: float2-aligned; conflict-free per 16-lane phase

// Scratch buffers (device globals)
__device__ float g_x0[NPX*NUc];
__device__ float g_x1[NPX*NUc];
__device__ float g_q [NPX*NUc];
__device__ float g_k [NPX*NUc];
__device__ float g_v [NPX*NUc];

__device__ __forceinline__ float sigf(float x) {
    return __fdividef(1.0f, 1.0f + __expf(-x));
}
__device__ __forceinline__ float tanh_fast(float x) {
    // tanh(x) = 2*sigmoid(2x) - 1
    return fmaf(2.0f, __fdividef(1.0f, 1.0f + __expf(-2.0f*x)), -1.0f);
}

// ---------------------------------------------------------------------------
// Fused LSTM: input build + 2 bidirectional layers. Block per sequence (w).
// 128 threads. Pregates: 96 threads (dir,gate). Recurrence: warp0=fwd,
// warp1=bwd, pure shfl (no block barriers inside the time loop).
// ---------------------------------------------------------------------------
__global__ void __launch_bounds__(128)
lstm_kernel(const float* __restrict__ features,   // (1,64,48,88)
            const int*   __restrict__ condition,  // (1,64,88)
            const float* __restrict__ mask,       // (1,64,88)
            const float* __restrict__ emb,        // (5,4)
            const float* __restrict__ wih0,       // (2,48,53)
            const float* __restrict__ whh0,       // (2,48,12)
            const float* __restrict__ bih0,       // (2,48)
            const float* __restrict__ bhh0,       // (2,48)
            const float* __restrict__ wih1,       // (2,48,24)
            const float* __restrict__ whh1,       // (2,48,12)
            const float* __restrict__ bih1,       // (2,48)
            const float* __restrict__ bhh1)       // (2,48)
{
    const int w   = blockIdx.x;
    const int tid = threadIdx.x;

    __shared__ float xs  [TT][CIN];
    __shared__ float pre [TT][96];
    __shared__ float hbuf[TT][2*HLc];

    // ---- build input sequence ----
    for (int idx = tid; idx < TT*CIN; idx += 128) {
        int t = idx / CIN, c = idx % CIN;
        float val;
        if (c < HPc)            val = features[(t*HPc + c)*WW + w];
        else if (c < HPc + 4)   val = emb[condition[t*WW + w]*4 + (c - HPc)];
        else                    val = mask[t*WW + w];
        xs[t][c] = val;
    }
    __syncthreads();

    // ---- layer-0 pregates ----
    if (tid < 96) {
        const int dir = tid / G4, g = tid % G4;
        float wr[CIN];
        const float* wrow = wih0 + (dir*G4 + g)*CIN;
        #pragma unroll
        for (int c = 0; c < CIN; c++) wr[c] = wrow[c];
        const float b = bih0[dir*G4 + g] + bhh0[dir*G4 + g];
        for (int t = 0; t < TT; t++) {
            float a0 = b, a1 = 0.f, a2 = 0.f, a3 = 0.f;
            #pragma unroll
            for (int c = 0; c < 52; c += 4) {
                a0 = fmaf(xs[t][c+0], wr[c+0], a0);
                a1 = fmaf(xs[t][c+1], wr[c+1], a1);
                a2 = fmaf(xs[t][c+2], wr[c+2], a2);
                a3 = fmaf(xs[t][c+3], wr[c+3], a3);
            }
            a0 = fmaf(xs[t][52], wr[52], a0);
            pre[t][tid] = (a0 + a1) + (a2 + a3);
        }
    }
    __syncthreads();

    // ---- layer-0 recurrence (warp 0 = fwd, warp 1 = bwd) ----
    if (tid < 64) {
        const int dir = tid >> 5, u = tid & 31;
        float wi[HLc], wf[HLc], wg[HLc], wo[HLc];
        if (u < HLc) {
            #pragma unroll
            for (int c = 0; c < HLc; c++) {
                wi[c] = whh0[(dir*G4      + u)*HLc + c];
                wf[c] = whh0[(dir*G4 + 12 + u)*HLc + c];
                wg[c] = whh0[(dir*G4 + 24 + u)*HLc + c];
                wo[c] = whh0[(dir*G4 + 36 + u)*HLc + c];
            }
        } else {
            #pragma unroll
            for (int c = 0; c < HLc; c++) { wi[c]=wf[c]=wg[c]=wo[c]=0.f; }
        }
        float h = 0.f, cs = 0.f;
        for (int s = 0; s < TT; s++) {
            const int t = dir ? (TT - 1 - s) : s;
            float gi, gf, gg, go;
            if (u < HLc) {
                gi = pre[t][dir*G4      + u];
                gf = pre[t][dir*G4 + 12 + u];
                gg = pre[t][dir*G4 + 24 + u];
                go = pre[t][dir*G4 + 36 + u];
            } else { gi = gf = gg = go = 0.f; }
            #pragma unroll
            for (int c = 0; c < HLc; c++) {
                float hc = __shfl_sync(0xffffffffu, h, c);
                gi = fmaf(hc, wi[c], gi);
                gf = fmaf(hc, wf[c], gf);
                gg = fmaf(hc, wg[c], gg);
                go = fmaf(hc, wo[c], go);
            }
            cs = sigf(gf)*cs + sigf(gi)*tanh_fast(gg);
            h  = sigf(go)*tanh_fast(cs);
            if (u < HLc) hbuf[t][dir*HLc + u] = h;
        }
    }
    __syncthreads();

    // ---- layer-1 pregates ----
    if (tid < 96) {
        const int dir = tid / G4, g = tid % G4;
        float wr[2*HLc];
        const float* wrow = wih1 + (dir*G4 + g)*(2*HLc);
        #pragma unroll
        for (int c = 0; c < 2*HLc; c++) wr[c] = wrow[c];
        const float b = bih1[dir*G4 + g] + bhh1[dir*G4 + g];
        for (int t = 0; t < TT; t++) {
            float a0 = b, a1 = 0.f, a2 = 0.f, a3 = 0.f;
            #pragma unroll
            for (int c = 0; c < 2*HLc; c += 4) {
                a0 = fmaf(hbuf[t][c+0], wr[c+0], a0);
                a1 = fmaf(hbuf[t][c+1], wr[c+1], a1);
                a2 = fmaf(hbuf[t][c+2], wr[c+2], a2);
                a3 = fmaf(hbuf[t][c+3], wr[c+3], a3);
            }
            pre[t][tid] = (a0 + a1) + (a2 + a3);
        }
    }
    __syncthreads();

    // ---- layer-1 recurrence ----
    if (tid < 64) {
        const int dir = tid >> 5, u = tid & 31;
        float wi[HLc], wf[HLc], wg[HLc], wo[HLc];
        if (u < HLc) {
            #pragma unroll
            for (int c = 0; c < HLc; c++) {
                wi[c] = whh1[(dir*G4      + u)*HLc + c];
                wf[c] = whh1[(dir*G4 + 12 + u)*HLc + c];
                wg[c] = whh1[(dir*G4 + 24 + u)*HLc + c];
                wo[c] = whh1[(dir*G4 + 36 + u)*HLc + c];
            }
        } else {
            #pragma unroll
            for (int c = 0; c < HLc; c++) { wi[c]=wf[c]=wg[c]=wo[c]=0.f; }
        }
        float h = 0.f, cs = 0.f;
        for (int s = 0; s < TT; s++) {
            const int t = dir ? (TT - 1 - s) : s;
            float gi, gf, gg, go;
            if (u < HLc) {
                gi = pre[t][dir*G4      + u];
                gf = pre[t][dir*G4 + 12 + u];
                gg = pre[t][dir*G4 + 24 + u];
                go = pre[t][dir*G4 + 36 + u];
            } else { gi = gf = gg = go = 0.f; }
            #pragma unroll
            for (int c = 0; c < HLc; c++) {
                float hc = __shfl_sync(0xffffffffu, h, c);
                gi = fmaf(hc, wi[c], gi);
                gf = fmaf(hc, wf[c], gf);
                gg = fmaf(hc, wg[c], gg);
                go = fmaf(hc, wo[c], go);
            }
            cs = sigf(gf)*cs + sigf(gi)*tanh_fast(gg);
            h  = sigf(go)*tanh_fast(cs);
            if (u < HLc) g_x0[(t*WW + w)*NUc + dir*HLc + u] = h;
        }
    }
}

// ---------------------------------------------------------------------------
// QKV projection: one thread per (e, pixel). 132 blocks x 128 threads.
// ---------------------------------------------------------------------------
__global__ void __launch_bounds__(128)
qkv_kernel(const float* __restrict__ x,
           const float* __restrict__ qw,   // (72,24)
           const float* __restrict__ qb)   // (72,)
{
    __shared__ float wsh[72*24];
    __shared__ float bsh[72];
    const int tid = threadIdx.x;
    for (int i = tid; i < 72*24; i += 128) wsh[i] = qw[i];
    if (tid < 72) bsh[tid] = qb[tid];
    __syncthreads();

    const int idx = blockIdx.x*128 + tid;        // 132*128 = 3*NPX exactly
    const int e  = idx / NPX;                    // block-uniform (5632%128==0)
    const int px = idx % NPX;

    float xr[NUc];
    const float4* xp = (const float4*)(x + px*NUc);
    #pragma unroll
    for (int f = 0; f < 6; f++) {
        float4 t = xp[f];
        xr[f*4+0]=t.x; xr[f*4+1]=t.y; xr[f*4+2]=t.z; xr[f*4+3]=t.w;
    }

    float acc[NUc];
    #pragma unroll
    for (int oc = 0; oc < NUc; oc++) acc[oc] = bsh[e*NUc + oc];
    #pragma unroll
    for (int c = 0; c < NUc; c++) {
        float xv = xr[c];
        #pragma unroll
        for (int oc = 0; oc < NUc; oc++)
            acc[oc] = fmaf(xv, wsh[(e*NUc + oc)*NUc + c], acc[oc]);
    }

    float scale = (e == 0) ? 0.4082482904638631f : 1.0f;
    float* dst = (e == 0) ? g_q : (e == 1) ? g_k : g_v;
    float4* dp = (float4*)(dst + px*NUc);
    #pragma unroll
    for (int f = 0; f < 6; f++) {
        float4 t;
        t.x = acc[f*4+0]*scale; t.y = acc[f*4+1]*scale;
        t.z = acc[f*4+2]*scale; t.w = acc[f*4+3]*scale;
        dp[f] = t;
    }
}

// ---------------------------------------------------------------------------
// NATTEN-2D, single-pass online softmax, fused proj (+ optional final head).
// Block = (row i, 8 cols) x 4 heads = 32 warps, 1024 threads.
// ---------------------------------------------------------------------------
__global__ void __launch_bounds__(1024)
natten_kernel(const float* __restrict__ rpb,   // (4,49,49)
              const float* __restrict__ pw,    // (24,24)
              const float* __restrict__ pb,    // (24,)
              const float* __restrict__ ow,    // (5,24)  (final only)
              const float* __restrict__ ob,    // (5,)    (final only)
              float* __restrict__ out,         // 24ch buffer OR 5ch d_out
              int final_mode)
{
    const int i  = blockIdx.y;
    const int j0 = blockIdx.x * 8;
    extern __shared__ float sm[];
    float* ks = sm;                          // [25*32][PITCH]
    float* vs = sm + KK*32*PITCH;            // [25*32][PITCH]
    float* ao = vs + KK*32*PITCH;            // [8][24]
    float* po = ao + 8*NUc;                  // [8][24]

    const int si      = min(max(i  - 12, 0), TT - KK);
    const int sj_min  = min(max(j0 - 12, 0), WW - KK);
    const int sj_last = min(max(j0 + 7 - 12, 0), WW - KK);
    const int ncols   = sj_last + KK - sj_min;                 // <= 32

    const int tid = threadIdx.x;

    // stage K/V union window: float4 global loads, float2 smem stores
    const int npx = KK * ncols;
    for (int idx = tid; idx < npx*6; idx += 1024) {
        int px = idx / 6, f4 = idx % 6;
        int a = px / ncols, c = px % ncols;
        int gpx = (si + a)*WW + (sj_min + c);
        float4 kd = *(const float4*)(g_k + gpx*NUc + f4*4);
        float4 vd = *(const float4*)(g_v + gpx*NUc + f4*4);
        float* kdst = ks + (a*32 + c)*PITCH + f4*4;
        float* vdst = vs + (a*32 + c)*PITCH + f4*4;
        *(float2*)(kdst)     = make_float2(kd.x, kd.y);
        *(float2*)(kdst + 2) = make_float2(kd.z, kd.w);
        *(float2*)(vdst)     = make_float2(vd.x, vd.y);
        *(float2*)(vdst + 2) = make_float2(vd.z, vd.w);
    }
    __syncthreads();

    const int warp = tid >> 5, lane = tid & 31;
    const int p = warp >> 2;           // pixel within tile 0..7
    const int n = warp & 3;            // head
    const int j = j0 + p;
    const int sj = min(max(j - 12, 0), WW - KK);
    const int colbase = sj - sj_min;   // 0..7
    const int ra0 = si - i + (KK - 1);
    const int rc0 = sj - j + (KK - 1);
    const float* rp = rpb + n*49*49;

    float qr[HDd];
    {
        const float* qp = g_q + ((i*WW + j)*NUc + n*HDd);
        #pragma unroll
        for (int d = 0; d < HDd; d++) qr[d] = qp[d];
    }

    // single pass: per-lane online softmax + V accumulation
    float m = -1e30f, s = 0.f;
    float o0=0.f,o1=0.f,o2=0.f,o3=0.f,o4=0.f,o5=0.f;
    #pragma unroll
    for (int e0 = 0; e0 < 20; e0++) {
        int e = lane + e0*32;
        if (e < KK*KK) {
            int a = e / KK, c = e - a*KK;
            const float* kp = ks + (a*32 + colbase + c)*PITCH + n*HDd;
            const float* vp = vs + (a*32 + colbase + c)*PITCH + n*HDd;
            float2 k01 = *(const float2*)(kp);
            float2 k23 = *(const float2*)(kp + 2);
            float2 k45 = *(const float2*)(kp + 4);
            float lg = __ldg(rp + (ra0 + a)*49 + (rc0 + c));
            lg = fmaf(qr[0], k01.x, lg);
            lg = fmaf(qr[1], k01.y, lg);
            lg = fmaf(qr[2], k23.x, lg);
            lg = fmaf(qr[3], k23.y, lg);
            lg = fmaf(qr[4], k45.x, lg);
            lg = fmaf(qr[5], k45.y, lg);
            float mn = fmaxf(m, lg);
            float cf = __expf(m - mn);
            float pr = __expf(lg - mn);
            m = mn;
            s = fmaf(s, cf, pr);
            float2 v01 = *(const float2*)(vp);
            float2 v23 = *(const float2*)(vp + 2);
            float2 v45 = *(const float2*)(vp + 4);
            o0 = fmaf(o0, cf, pr*v01.x);
            o1 = fmaf(o1, cf, pr*v01.y);
            o2 = fmaf(o2, cf, pr*v23.x);
            o3 = fmaf(o3, cf, pr*v23.y);
            o4 = fmaf(o4, cf, pr*v45.x);
            o5 = fmaf(o5, cf, pr*v45.y);
        }
    }
    // cross-lane merge of (m, s, o[6])
    #pragma unroll
    for (int off = 16; off > 0; off >>= 1) {
        float mo = __shfl_xor_sync(0xffffffffu, m, off);
        float so = __shfl_xor_sync(0xffffffffu, s, off);
        float q0 = __shfl_xor_sync(0xffffffffu, o0, off);
        float q1 = __shfl_xor_sync(0xffffffffu, o1, off);
        float q2 = __shfl_xor_sync(0xffffffffu, o2, off);
        float q3 = __shfl_xor_sync(0xffffffffu, o3, off);
        float q4 = __shfl_xor_sync(0xffffffffu, o4, off);
        float q5 = __shfl_xor_sync(0xffffffffu, o5, off);
        float mn = fmaxf(m, mo);
        float fa = __expf(m  - mn);
        float fb = __expf(mo - mn);
        m = mn;
        s = s*fa + so*fb;
        o0 = o0*fa + q0*fb;
        o1 = o1*fa + q1*fb;
        o2 = o2*fa + q2*fb;
        o3 = o3*fa + q3*fb;
        o4 = o4*fa + q4*fb;
        o5 = o5*fa + q5*fb;
    }
    if (lane == 0) {
        float inv = 1.0f / s;
        float* dst = ao + p*NUc + n*HDd;
        dst[0]=o0*inv; dst[1]=o1*inv; dst[2]=o2*inv;
        dst[3]=o3*inv; dst[4]=o4*inv; dst[5]=o5*inv;
    }
    __syncthreads();

    // fused output projection (24x24)
    if (tid < 8*NUc) {
        int pp = tid / NUc, oc = tid % NUc;
        float acc = __ldg(pb + oc);
        const float* wrow = pw + oc*NUc;
        #pragma unroll
        for (int ic = 0; ic < NUc; ic++)
            acc = fmaf(ao[pp*NUc + ic], __ldg(wrow + ic), acc);
        if (!final_mode) out[(i*WW + j0 + pp)*NUc + oc] = acc;
        else             po[pp*NUc + oc] = acc;
    }
    if (final_mode) {
        __syncthreads();
        if (tid < 8*5) {
            int pp = tid / 5, r = tid % 5;
            float acc = __ldg(ob + r);
            const float* wrow = ow + r*NUc;
            #pragma unroll
            for (int ic = 0; ic < NUc; ic++)
                acc = fmaf(po[pp*NUc + ic], __ldg(wrow + ic), acc);
            out[(i*WW + j0 + pp)*5 + r] = acc;
        }
    }
}

// ---------------------------------------------------------------------------
extern "C" void kernel_launch(void* const* d_in, const int* in_sizes, int n_in,
                              void* d_out, int out_size)
{
    const float* features  = (const float*)d_in[0];
    const int*   condition = (const int*)  d_in[1];
    const float* mask      = (const float*)d_in[2];
    const float* emb       = (const float*)d_in[3];
    const float* wih0      = (const float*)d_in[4];
    const float* whh0      = (const float*)d_in[5];
    const float* bih0      = (const float*)d_in[6];
    const float* bhh0      = (const float*)d_in[7];
    const float* wih1      = (const float*)d_in[8];
    const float* whh1      = (const float*)d_in[9];
    const float* bih1      = (const float*)d_in[10];
    const float* bhh1      = (const float*)d_in[11];
    const float* qkv_w     = (const float*)d_in[12];
    const float* qkv_b     = (const float*)d_in[13];
    const float* rpb       = (const float*)d_in[14];
    const float* proj_w    = (const float*)d_in[15];
    const float* proj_b    = (const float*)d_in[16];
    const float* out_w     = (const float*)d_in[17];
    const float* out_b     = (const float*)d_in[18];
    float* out = (float*)d_out;

    float *px0 = nullptr, *px1 = nullptr;
    cudaGetSymbolAddress((void**)&px0, g_x0);
    cudaGetSymbolAddress((void**)&px1, g_x1);

    const int natten_smem = (2*KK*32*PITCH + 2*8*NUc) * (int)sizeof(float); // 167936 B
    cudaFuncSetAttribute(natten_kernel,
                         cudaFuncAttributeMaxDynamicSharedMemorySize, natten_smem);

    // 1) fused LSTM
    lstm_kernel<<<WW, 128>>>(features, condition, mask, emb,
                             wih0, whh0, bih0, bhh0,
                             wih1, whh1, bih1, bhh1);

    dim3 ngrid(WW/8, TT);

    // 2) NATTEN layer 1
    qkv_kernel<<<132, 128>>>(px0, qkv_w, qkv_b);
    natten_kernel<<<ngrid, 1024, natten_smem>>>(rpb, proj_w, proj_b,
                                                out_w, out_b, px1, 0);

    // 3) NATTEN layer 2 + fused head -> d_out
    qkv_kernel<<<132, 128>>>(px1, qkv_w, qkv_b);
    natten_kernel<<<ngrid, 1024, natten_smem>>>(rpb, proj_w, proj_b,
                                                out_w, out_b, out, 1);
}

// round 4
// speedup vs baseline: 1.1999x; 1.1999x over previous
#include <cuda_runtime.h>
#include <cuda_bf16.h>

// Problem constants
#define TT   64
#define WW   88
#define HPc  48
#define CIN  53
#define HLc  12
#define G4   48
#define NHh  4
#define HDd  6
#define NUc  24
#define KK   25
#define NPX  (TT*WW)   // 5632
#define PITCH 25       // odd -> conflict-free scalar LDS

// Scratch buffers (device globals)
__device__ float g_x0[NPX*NUc];
__device__ float g_x1[NPX*NUc];
__device__ float g_q [NPX*NUc];
__device__ float g_k [NPX*NUc];
__device__ float g_v [NPX*NUc];

__device__ __forceinline__ float sigf(float x) {
    return 1.0f / (1.0f + __expf(-x));
}

// ---------------------------------------------------------------------------
// Fused LSTM (R2 version — known good): block per sequence, 96 threads.
// ---------------------------------------------------------------------------
__global__ void __launch_bounds__(96)
lstm_kernel(const float* __restrict__ features,
            const int*   __restrict__ condition,
            const float* __restrict__ mask,
            const float* __restrict__ emb,
            const float* __restrict__ wih0,
            const float* __restrict__ whh0,
            const float* __restrict__ bih0,
            const float* __restrict__ bhh0,
            const float* __restrict__ wih1,
            const float* __restrict__ whh1,
            const float* __restrict__ bih1,
            const float* __restrict__ bhh1)
{
    const int w   = blockIdx.x;
    const int tid = threadIdx.x;
    const int dir = tid / G4;
    const int g   = tid % G4;
    const int u   = g % HLc;

    __shared__ float xs  [TT][CIN];
    __shared__ float preg[TT][96];
    __shared__ float hbuf[TT][2*HLc];
    __shared__ float hcur[2][HLc];
    __shared__ float ccur[2][HLc];

    for (int idx = tid; idx < TT*CIN; idx += 96) {
        int t = idx / CIN, c = idx % CIN;
        float val;
        if (c < HPc)            val = features[(t*HPc + c)*WW + w];
        else if (c < HPc + 4)   val = emb[condition[t*WW + w]*4 + (c - HPc)];
        else                    val = mask[t*WW + w];
        xs[t][c] = val;
    }
    __syncthreads();

    {
        float wr[CIN];
        const float* wrow = wih0 + (dir*G4 + g)*CIN;
        #pragma unroll
        for (int c = 0; c < CIN; c++) wr[c] = wrow[c];
        const float b = bih0[dir*G4 + g] + bhh0[dir*G4 + g];
        for (int t = 0; t < TT; t++) {
            float acc = b;
            #pragma unroll
            for (int c = 0; c < CIN; c++) acc = fmaf(xs[t][c], wr[c], acc);
            preg[t][tid] = acc;
        }
    }
    if (g < HLc) { hcur[dir][u] = 0.f; ccur[dir][u] = 0.f; }
    __syncthreads();

    {
        float wr[HLc];
        const float* wrow = whh0 + (dir*G4 + g)*HLc;
        #pragma unroll
        for (int c = 0; c < HLc; c++) wr[c] = wrow[c];
        for (int s = 0; s < TT; s++) {
            const int t = dir ? (TT - 1 - s) : s;
            float acc = preg[t][tid];
            #pragma unroll
            for (int c = 0; c < HLc; c++) acc = fmaf(hcur[dir][c], wr[c], acc);
            preg[t][tid] = acc;
            __syncthreads();
            if (g < HLc) {
                float gi = preg[t][dir*G4 +      u];
                float gf = preg[t][dir*G4 + 12 + u];
                float gg = preg[t][dir*G4 + 24 + u];
                float go = preg[t][dir*G4 + 36 + u];
                float cn = sigf(gf)*ccur[dir][u] + sigf(gi)*tanhf(gg);
                float hn = sigf(go)*tanhf(cn);
                ccur[dir][u] = cn;
                hcur[dir][u] = hn;
                hbuf[t][dir*HLc + u] = hn;
            }
            __syncthreads();
        }
    }

    {
        float wr[2*HLc];
        const float* wrow = wih1 + (dir*G4 + g)*(2*HLc);
        #pragma unroll
        for (int c = 0; c < 2*HLc; c++) wr[c] = wrow[c];
        const float b = bih1[dir*G4 + g] + bhh1[dir*G4 + g];
        for (int t = 0; t < TT; t++) {
            float acc = b;
            #pragma unroll
            for (int c = 0; c < 2*HLc; c++) acc = fmaf(hbuf[t][c], wr[c], acc);
            preg[t][tid] = acc;
        }
    }
    if (g < HLc) { hcur[dir][u] = 0.f; ccur[dir][u] = 0.f; }
    __syncthreads();

    {
        float wr[HLc];
        const float* wrow = whh1 + (dir*G4 + g)*HLc;
        #pragma unroll
        for (int c = 0; c < HLc; c++) wr[c] = wrow[c];
        for (int s = 0; s < TT; s++) {
            const int t = dir ? (TT - 1 - s) : s;
            float acc = preg[t][tid];
            #pragma unroll
            for (int c = 0; c < HLc; c++) acc = fmaf(hcur[dir][c], wr[c], acc);
            preg[t][tid] = acc;
            __syncthreads();
            if (g < HLc) {
                float gi = preg[t][dir*G4 +      u];
                float gf = preg[t][dir*G4 + 12 + u];
                float gg = preg[t][dir*G4 + 24 + u];
                float go = preg[t][dir*G4 + 36 + u];
                float cn = sigf(gf)*ccur[dir][u] + sigf(gi)*tanhf(gg);
                float hn = sigf(go)*tanhf(cn);
                ccur[dir][u] = cn;
                hcur[dir][u] = hn;
                g_x0[(t*WW + w)*NUc + dir*HLc + u] = hn;
            }
            __syncthreads();
        }
    }
}

// ---------------------------------------------------------------------------
// QKV projection: one thread per (e, pixel, half) -> 12 output channels.
// 33792 threads = 132 blocks x 256. e and weights block-uniform.
// ---------------------------------------------------------------------------
__global__ void __launch_bounds__(256)
qkv_kernel(const float* __restrict__ x,
           const float* __restrict__ qw,   // (72,24)
           const float* __restrict__ qb)   // (72,)
{
    __shared__ float wsh[72*24];
    __shared__ float bsh[72];
    const int tid = threadIdx.x;
    for (int i = tid; i < 72*24; i += 256) wsh[i] = qw[i];
    if (tid < 72) bsh[tid] = qb[tid];
    __syncthreads();

    const int idx  = blockIdx.x*256 + tid;     // 132*256 = 2*3*NPX exactly
    const int half = idx & 1;
    const int px   = (idx >> 1) % NPX;
    const int e    = idx / (2*NPX);            // 0=q,1=k,2=v (block-uniform)

    float xr[NUc];
    const float4* xp = (const float4*)(x + px*NUc);
    #pragma unroll
    for (int f = 0; f < 6; f++) {
        float4 t = xp[f];
        xr[f*4+0]=t.x; xr[f*4+1]=t.y; xr[f*4+2]=t.z; xr[f*4+3]=t.w;
    }

    const int oc0 = e*NUc + half*12;
    float acc[12];
    #pragma unroll
    for (int oc = 0; oc < 12; oc++) acc[oc] = bsh[oc0 + oc];
    #pragma unroll
    for (int c = 0; c < NUc; c++) {
        float xv = xr[c];
        #pragma unroll
        for (int oc = 0; oc < 12; oc++)
            acc[oc] = fmaf(xv, wsh[(oc0 + oc)*NUc + c], acc[oc]);
    }

    float scale = (e == 0) ? 0.4082482904638631f : 1.0f;
    float* dst = (e == 0) ? g_q : (e == 1) ? g_k : g_v;
    float4* dp = (float4*)(dst + px*NUc + half*12);
    #pragma unroll
    for (int f = 0; f < 3; f++) {
        float4 t;
        t.x = acc[f*4+0]*scale; t.y = acc[f*4+1]*scale;
        t.z = acc[f*4+2]*scale; t.w = acc[f*4+3]*scale;
        dp[f] = t;
    }
}

// ---------------------------------------------------------------------------
// NATTEN-2D: two-pass with logit RECOMPUTE (no lg[] array -> no spills,
// independent exps -> pipelined MUFU). Fused proj (+ optional final head).
// ---------------------------------------------------------------------------
__global__ void __launch_bounds__(1024)
natten_kernel(const float* __restrict__ rpb,   // (4,49,49)
              const float* __restrict__ pw,    // (24,24)
              const float* __restrict__ pb,    // (24,)
              const float* __restrict__ ow,    // (5,24)
              const float* __restrict__ ob,    // (5,)
              float* __restrict__ out,
              int final_mode)
{
    const int i  = blockIdx.y;
    const int j0 = blockIdx.x * 8;
    extern __shared__ float sm[];
    float* ks = sm;                          // [25*32][PITCH]
    float* vs = sm + KK*32*PITCH;
    float* ao = vs + KK*32*PITCH;            // [8][24]
    float* po = ao + 8*NUc;                  // [8][24]

    const int si      = min(max(i  - 12, 0), TT - KK);
    const int sj_min  = min(max(j0 - 12, 0), WW - KK);
    const int sj_last = min(max(j0 + 7 - 12, 0), WW - KK);
    const int ncols   = sj_last + KK - sj_min;                 // <= 32

    const int tid = threadIdx.x;

    const int npx = KK * ncols;
    for (int idx = tid; idx < npx*6; idx += 1024) {
        int px = idx / 6, f4 = idx % 6;
        int a = px / ncols, c = px % ncols;
        int gpx = (si + a)*WW + (sj_min + c);
        float4 kd = *(const float4*)(g_k + gpx*NUc + f4*4);
        float4 vd = *(const float4*)(g_v + gpx*NUc + f4*4);
        float* kdst = ks + (a*32 + c)*PITCH + f4*4;
        float* vdst = vs + (a*32 + c)*PITCH + f4*4;
        kdst[0]=kd.x; kdst[1]=kd.y; kdst[2]=kd.z; kdst[3]=kd.w;
        vdst[0]=vd.x; vdst[1]=vd.y; vdst[2]=vd.z; vdst[3]=vd.w;
    }
    __syncthreads();

    const int warp = tid >> 5, lane = tid & 31;
    const int p = warp >> 2;
    const int n = warp & 3;
    const int j = j0 + p;
    const int sj = min(max(j - 12, 0), WW - KK);
    const int colbase = sj - sj_min;
    const int ra0 = si - i + (KK - 1);
    const int rc0 = sj - j + (KK - 1);
    const float* rp = rpb + n*49*49;

    float qr[HDd];
    {
        const float* qp = g_q + ((i*WW + j)*NUc + n*HDd);
        #pragma unroll
        for (int d = 0; d < HDd; d++) qr[d] = qp[d];
    }

    // pass 1: max of logits (no storage)
    float lmax = -1e30f;
    #pragma unroll
    for (int e0 = 0; e0 < 20; e0++) {
        int e = lane + e0*32;
        if (e < KK*KK) {
            int a = e / KK, c = e - a*KK;
            const float* kp = ks + (a*32 + colbase + c)*PITCH + n*HDd;
            float lg = __ldg(rp + (ra0 + a)*49 + (rc0 + c));
            #pragma unroll
            for (int d = 0; d < HDd; d++) lg = fmaf(qr[d], kp[d], lg);
            lmax = fmaxf(lmax, lg);
        }
    }
    #pragma unroll
    for (int o = 16; o > 0; o >>= 1)
        lmax = fmaxf(lmax, __shfl_xor_sync(0xffffffffu, lmax, o));

    // pass 2: recompute logits, exp (independent), accumulate V
    float sum = 0.f;
    float oacc[HDd] = {0.f,0.f,0.f,0.f,0.f,0.f};
    #pragma unroll
    for (int e0 = 0; e0 < 20; e0++) {
        int e = lane + e0*32;
        if (e < KK*KK) {
            int a = e / KK, c = e - a*KK;
            const int base = (a*32 + colbase + c)*PITCH + n*HDd;
            const float* kp = ks + base;
            float lg = __ldg(rp + (ra0 + a)*49 + (rc0 + c));
            #pragma unroll
            for (int d = 0; d < HDd; d++) lg = fmaf(qr[d], kp[d], lg);
            float pr = __expf(lg - lmax);
            sum += pr;
            const float* vp = vs + base;
            #pragma unroll
            for (int d = 0; d < HDd; d++) oacc[d] = fmaf(pr, vp[d], oacc[d]);
        }
    }
    #pragma unroll
    for (int o = 16; o > 0; o >>= 1) {
        sum += __shfl_xor_sync(0xffffffffu, sum, o);
        #pragma unroll
        for (int d = 0; d < HDd; d++)
            oacc[d] += __shfl_xor_sync(0xffffffffu, oacc[d], o);
    }
    if (lane == 0) {
        float inv = 1.0f / sum;
        #pragma unroll
        for (int d = 0; d < HDd; d++) ao[p*NUc + n*HDd + d] = oacc[d]*inv;
    }
    __syncthreads();

    // fused output projection (24x24)
    if (tid < 8*NUc) {
        int pp = tid / NUc, oc = tid % NUc;
        float acc = __ldg(pb + oc);
        const float* wrow = pw + oc*NUc;
        #pragma unroll
        for (int ic = 0; ic < NUc; ic++)
            acc = fmaf(ao[pp*NUc + ic], __ldg(wrow + ic), acc);
        if (!final_mode) out[(i*WW + j0 + pp)*NUc + oc] = acc;
        else             po[pp*NUc + oc] = acc;
    }
    if (final_mode) {
        __syncthreads();
        if (tid < 8*5) {
            int pp = tid / 5, r = tid % 5;
            float acc = __ldg(ob + r);
            const float* wrow = ow + r*NUc;
            #pragma unroll
            for (int ic = 0; ic < NUc; ic++)
                acc = fmaf(po[pp*NUc + ic], __ldg(wrow + ic), acc);
            out[(i*WW + j0 + pp)*5 + r] = acc;
        }
    }
}

// ---------------------------------------------------------------------------
extern "C" void kernel_launch(void* const* d_in, const int* in_sizes, int n_in,
                              void* d_out, int out_size)
{
    const float* features  = (const float*)d_in[0];
    const int*   condition = (const int*)  d_in[1];
    const float* mask      = (const float*)d_in[2];
    const float* emb       = (const float*)d_in[3];
    const float* wih0      = (const float*)d_in[4];
    const float* whh0      = (const float*)d_in[5];
    const float* bih0      = (const float*)d_in[6];
    const float* bhh0      = (const float*)d_in[7];
    const float* wih1      = (const float*)d_in[8];
    const float* whh1      = (const float*)d_in[9];
    const float* bih1      = (const float*)d_in[10];
    const float* bhh1      = (const float*)d_in[11];
    const float* qkv_w     = (const float*)d_in[12];
    const float* qkv_b     = (const float*)d_in[13];
    const float* rpb       = (const float*)d_in[14];
    const float* proj_w    = (const float*)d_in[15];
    const float* proj_b    = (const float*)d_in[16];
    const float* out_w     = (const float*)d_in[17];
    const float* out_b     = (const float*)d_in[18];
    float* out = (float*)d_out;

    float *px0 = nullptr, *px1 = nullptr;
    cudaGetSymbolAddress((void**)&px0, g_x0);
    cudaGetSymbolAddress((void**)&px1, g_x1);

    const int natten_smem = (2*KK*32*PITCH + 2*8*NUc) * (int)sizeof(float); // 161536 B
    cudaFuncSetAttribute(natten_kernel,
                         cudaFuncAttributeMaxDynamicSharedMemorySize, natten_smem);

    // 1) fused LSTM
    lstm_kernel<<<WW, 96>>>(features, condition, mask, emb,
                            wih0, whh0, bih0, bhh0,
                            wih1, whh1, bih1, bhh1);

    dim3 ngrid(WW/8, TT);

    // 2) NATTEN layer 1
    qkv_kernel<<<132, 256>>>(px0, qkv_w, qkv_b);
    natten_kernel<<<ngrid, 1024, natten_smem>>>(rpb, proj_w, proj_b,
                                                out_w, out_b, px1, 0);

    // 3) NATTEN layer 2 + fused head -> d_out
    qkv_kernel<<<132, 256>>>(px1, qkv_w, qkv_b);
    natten_kernel<<<ngrid, 1024, natten_smem>>>(rpb, proj_w, proj_b,
                                                out_w, out_b, out, 1);
}

// round 5
// speedup vs baseline: 1.5756x; 1.3130x over previous
#include <cuda_runtime.h>
#include <cuda_bf16.h>

// Problem constants
#define TT   64
#define WW   88
#define HPc  48
#define CIN  53
#define HLc  12
#define G4   48
#define NHh  4
#define HDd  6
#define NUc  24
#define KK   25
#define NPX  (TT*WW)   // 5632
#define PITCH 26       // float2-aligned; stride 13 float2 -> conflict-free

// Scratch buffers (device globals) — two full qkv sets (layer1 / layer2)
__device__ float g_q0[NPX*NUc];
__device__ float g_k0[NPX*NUc];
__device__ float g_v0[NPX*NUc];
__device__ float g_q1[NPX*NUc];
__device__ float g_k1[NPX*NUc];
__device__ float g_v1[NPX*NUc];

#define QSCALE 0.4082482904638631f

__device__ __forceinline__ float sigf(float x) {
    return __fdividef(1.0f, 1.0f + __expf(-x));
}
__device__ __forceinline__ float tanh_fast(float x) {
    return fmaf(2.0f, __fdividef(1.0f, 1.0f + __expf(-2.0f*x)), -1.0f);
}

// ---------------------------------------------------------------------------
// Fused: input build + 2 bidirectional LSTM layers + QKV for natten layer 1.
// Block per sequence (w), 96 threads. Recurrence: warp0=fwd, warp1=bwd, shfl.
// ---------------------------------------------------------------------------
__global__ void __launch_bounds__(96)
lstm_kernel(const float* __restrict__ features,
            const int*   __restrict__ condition,
            const float* __restrict__ mask,
            const float* __restrict__ emb,
            const float* __restrict__ wih0, const float* __restrict__ whh0,
            const float* __restrict__ bih0, const float* __restrict__ bhh0,
            const float* __restrict__ wih1, const float* __restrict__ whh1,
            const float* __restrict__ bih1, const float* __restrict__ bhh1,
            const float* __restrict__ qkv_w,  // (72,24)
            const float* __restrict__ qkv_b)  // (72,)
{
    const int w   = blockIdx.x;
    const int tid = threadIdx.x;

    __shared__ float xs  [TT][CIN];
    __shared__ float pre [TT][96];
    __shared__ float hbuf[TT][2*HLc];

    // ---- build input sequence ----
    for (int idx = tid; idx < TT*CIN; idx += 96) {
        int t = idx / CIN, c = idx % CIN;
        float val;
        if (c < HPc)            val = features[(t*HPc + c)*WW + w];
        else if (c < HPc + 4)   val = emb[condition[t*WW + w]*4 + (c - HPc)];
        else                    val = mask[t*WW + w];
        xs[t][c] = val;
    }
    __syncthreads();

    // ---- layer-0 pregates (96 threads) ----
    {
        const int dir = tid / G4, g = tid % G4;
        float wr[CIN];
        const float* wrow = wih0 + (dir*G4 + g)*CIN;
        #pragma unroll
        for (int c = 0; c < CIN; c++) wr[c] = wrow[c];
        const float b = bih0[dir*G4 + g] + bhh0[dir*G4 + g];
        for (int t = 0; t < TT; t++) {
            float a0 = b, a1 = 0.f, a2 = 0.f, a3 = 0.f;
            #pragma unroll
            for (int c = 0; c < 52; c += 4) {
                a0 = fmaf(xs[t][c+0], wr[c+0], a0);
                a1 = fmaf(xs[t][c+1], wr[c+1], a1);
                a2 = fmaf(xs[t][c+2], wr[c+2], a2);
                a3 = fmaf(xs[t][c+3], wr[c+3], a3);
            }
            a0 = fmaf(xs[t][52], wr[52], a0);
            pre[t][tid] = (a0 + a1) + (a2 + a3);
        }
    }
    __syncthreads();

    // ---- layer-0 recurrence (2 warps, shfl, no barriers) ----
    if (tid < 64) {
        const int dir = tid >> 5, u = tid & 31;
        float wi[HLc], wf[HLc], wg[HLc], wo[HLc];
        if (u < HLc) {
            #pragma unroll
            for (int c = 0; c < HLc; c++) {
                wi[c] = whh0[(dir*G4      + u)*HLc + c];
                wf[c] = whh0[(dir*G4 + 12 + u)*HLc + c];
                wg[c] = whh0[(dir*G4 + 24 + u)*HLc + c];
                wo[c] = whh0[(dir*G4 + 36 + u)*HLc + c];
            }
        } else {
            #pragma unroll
            for (int c = 0; c < HLc; c++) { wi[c]=wf[c]=wg[c]=wo[c]=0.f; }
        }
        float h = 0.f, cs = 0.f;
        for (int s = 0; s < TT; s++) {
            const int t = dir ? (TT - 1 - s) : s;
            float gi, gf, gg, go;
            if (u < HLc) {
                gi = pre[t][dir*G4      + u];
                gf = pre[t][dir*G4 + 12 + u];
                gg = pre[t][dir*G4 + 24 + u];
                go = pre[t][dir*G4 + 36 + u];
            } else { gi = gf = gg = go = 0.f; }
            #pragma unroll
            for (int c = 0; c < HLc; c++) {
                float hc = __shfl_sync(0xffffffffu, h, c);
                gi = fmaf(hc, wi[c], gi);
                gf = fmaf(hc, wf[c], gf);
                gg = fmaf(hc, wg[c], gg);
                go = fmaf(hc, wo[c], go);
            }
            cs = sigf(gf)*cs + sigf(gi)*tanh_fast(gg);
            h  = sigf(go)*tanh_fast(cs);
            if (u < HLc) hbuf[t][dir*HLc + u] = h;
        }
    }
    __syncthreads();

    // ---- layer-1 pregates ----
    {
        const int dir = tid / G4, g = tid % G4;
        float wr[2*HLc];
        const float* wrow = wih1 + (dir*G4 + g)*(2*HLc);
        #pragma unroll
        for (int c = 0; c < 2*HLc; c++) wr[c] = wrow[c];
        const float b = bih1[dir*G4 + g] + bhh1[dir*G4 + g];
        for (int t = 0; t < TT; t++) {
            float a0 = b, a1 = 0.f, a2 = 0.f, a3 = 0.f;
            #pragma unroll
            for (int c = 0; c < 2*HLc; c += 4) {
                a0 = fmaf(hbuf[t][c+0], wr[c+0], a0);
                a1 = fmaf(hbuf[t][c+1], wr[c+1], a1);
                a2 = fmaf(hbuf[t][c+2], wr[c+2], a2);
                a3 = fmaf(hbuf[t][c+3], wr[c+3], a3);
            }
            pre[t][tid] = (a0 + a1) + (a2 + a3);
        }
    }
    __syncthreads();

    // ---- layer-1 recurrence (writes hbuf, safe: pregates all done) ----
    if (tid < 64) {
        const int dir = tid >> 5, u = tid & 31;
        float wi[HLc], wf[HLc], wg[HLc], wo[HLc];
        if (u < HLc) {
            #pragma unroll
            for (int c = 0; c < HLc; c++) {
                wi[c] = whh1[(dir*G4      + u)*HLc + c];
                wf[c] = whh1[(dir*G4 + 12 + u)*HLc + c];
                wg[c] = whh1[(dir*G4 + 24 + u)*HLc + c];
                wo[c] = whh1[(dir*G4 + 36 + u)*HLc + c];
            }
        } else {
            #pragma unroll
            for (int c = 0; c < HLc; c++) { wi[c]=wf[c]=wg[c]=wo[c]=0.f; }
        }
        float h = 0.f, cs = 0.f;
        for (int s = 0; s < TT; s++) {
            const int t = dir ? (TT - 1 - s) : s;
            float gi, gf, gg, go;
            if (u < HLc) {
                gi = pre[t][dir*G4      + u];
                gf = pre[t][dir*G4 + 12 + u];
                gg = pre[t][dir*G4 + 24 + u];
                go = pre[t][dir*G4 + 36 + u];
            } else { gi = gf = gg = go = 0.f; }
            #pragma unroll
            for (int c = 0; c < HLc; c++) {
                float hc = __shfl_sync(0xffffffffu, h, c);
                gi = fmaf(hc, wi[c], gi);
                gf = fmaf(hc, wf[c], gf);
                gg = fmaf(hc, wg[c], gg);
                go = fmaf(hc, wo[c], go);
            }
            cs = sigf(gf)*cs + sigf(gi)*tanh_fast(gg);
            h  = sigf(go)*tanh_fast(cs);
            if (u < HLc) hbuf[t][dir*HLc + u] = h;
        }
    }
    __syncthreads();

    // ---- fused QKV for natten layer 1: threads 0..71 own one out-channel ----
    if (tid < 72) {
        float wr[NUc];
        const float* wrow = qkv_w + tid*NUc;
        #pragma unroll
        for (int c = 0; c < NUc; c++) wr[c] = wrow[c];
        const float b = qkv_b[tid];
        const int e  = tid / NUc;        // 0=q 1=k 2=v
        const int ch = tid % NUc;
        const float scale = (e == 0) ? QSCALE : 1.0f;
        float* dst = (e == 0) ? g_q0 : (e == 1) ? g_k0 : g_v0;
        for (int t = 0; t < TT; t++) {
            float a0 = b, a1 = 0.f, a2 = 0.f, a3 = 0.f;
            #pragma unroll
            for (int c = 0; c < NUc; c += 4) {
                a0 = fmaf(hbuf[t][c+0], wr[c+0], a0);
                a1 = fmaf(hbuf[t][c+1], wr[c+1], a1);
                a2 = fmaf(hbuf[t][c+2], wr[c+2], a2);
                a3 = fmaf(hbuf[t][c+3], wr[c+3], a3);
            }
            dst[(t*WW + w)*NUc + ch] = ((a0 + a1) + (a2 + a3)) * scale;
        }
    }
}

// ---------------------------------------------------------------------------
// NATTEN-2D: two-pass stored logits (R2 structure), float2 LDS, fused proj.
// mode 0: epilogue computes QKV for next layer -> g_{q,k,v}1.
// mode 1: epilogue computes final head (24->5) -> out.
// ---------------------------------------------------------------------------
__global__ void __launch_bounds__(1024)
natten_kernel(const float* __restrict__ qsrc,
              const float* __restrict__ ksrc,
              const float* __restrict__ vsrc,
              const float* __restrict__ rpb,    // (4,49,49)
              const float* __restrict__ pw,     // (24,24)
              const float* __restrict__ pb,     // (24,)
              const float* __restrict__ qkv_w,  // (72,24)   mode 0
              const float* __restrict__ qkv_b,  // (72,)     mode 0
              const float* __restrict__ ow,     // (5,24)    mode 1
              const float* __restrict__ ob,     // (5,)      mode 1
              float* __restrict__ out,          // mode1: (64,88,5)
              int mode)
{
    const int i  = blockIdx.y;
    const int j0 = blockIdx.x * 8;
    extern __shared__ float sm[];
    float* ks  = sm;                          // [25*32][PITCH]
    float* vs  = ks + KK*32*PITCH;
    float* ao  = vs + KK*32*PITCH;            // [8][24]
    float* po  = ao + 8*NUc;                  // [8][24]
    float* wsh = po + 8*NUc;                  // [72*24]
    float* bsh = wsh + 72*NUc;                // [72]

    const int si      = min(max(i  - 12, 0), TT - KK);
    const int sj_min  = min(max(j0 - 12, 0), WW - KK);
    const int sj_last = min(max(j0 + 7 - 12, 0), WW - KK);
    const int ncols   = sj_last + KK - sj_min;                 // <= 32

    const int tid = threadIdx.x;

    // stage epilogue weights
    if (mode == 0) {
        for (int x = tid; x < 72*NUc; x += 1024) wsh[x] = qkv_w[x];
        if (tid < 72) bsh[tid] = qkv_b[tid];
    }

    // stage K/V window: one pixel per thread (one divide per thread)
    const int npx = KK * ncols;
    for (int spx = tid; spx < npx; spx += 1024) {
        int a = spx / ncols, c = spx - a*ncols;
        int gpx = (si + a)*WW + (sj_min + c);
        float* kdst = ks + (a*32 + c)*PITCH;
        float* vdst = vs + (a*32 + c)*PITCH;
        const float4* kp = (const float4*)(ksrc + gpx*NUc);
        const float4* vp = (const float4*)(vsrc + gpx*NUc);
        #pragma unroll
        for (int f = 0; f < 6; f++) {
            float4 kd = kp[f];
            *(float2*)(kdst + f*4)     = make_float2(kd.x, kd.y);
            *(float2*)(kdst + f*4 + 2) = make_float2(kd.z, kd.w);
        }
        #pragma unroll
        for (int f = 0; f < 6; f++) {
            float4 vd = vp[f];
            *(float2*)(vdst + f*4)     = make_float2(vd.x, vd.y);
            *(float2*)(vdst + f*4 + 2) = make_float2(vd.z, vd.w);
        }
    }
    __syncthreads();

    const int warp = tid >> 5, lane = tid & 31;
    const int p = warp >> 2;
    const int n = warp & 3;
    const int j = j0 + p;
    const int sj = min(max(j - 12, 0), WW - KK);
    const int colbase = sj - sj_min;
    const int ra0 = si - i + (KK - 1);
    const int rc0 = sj - j + (KK - 1);
    const float* rp = rpb + n*49*49;

    float qr[HDd];
    {
        const float* qp = qsrc + ((i*WW + j)*NUc + n*HDd);
        #pragma unroll
        for (int d = 0; d < HDd; d++) qr[d] = qp[d];
    }

    // pass 1: store logits, track max
    float lg[20];
    float lmax = -1e30f;
    #pragma unroll
    for (int e0 = 0; e0 < 20; e0++) {
        int e = lane + e0*32;
        if (e < KK*KK) {
            int a = e / KK, c = e - a*KK;
            const float* kp = ks + (a*32 + colbase + c)*PITCH + n*HDd;
            float2 k01 = *(const float2*)(kp);
            float2 k23 = *(const float2*)(kp + 2);
            float2 k45 = *(const float2*)(kp + 4);
            float acc = __ldg(rp + (ra0 + a)*49 + (rc0 + c));
            acc = fmaf(qr[0], k01.x, acc);
            acc = fmaf(qr[1], k01.y, acc);
            acc = fmaf(qr[2], k23.x, acc);
            acc = fmaf(qr[3], k23.y, acc);
            acc = fmaf(qr[4], k45.x, acc);
            acc = fmaf(qr[5], k45.y, acc);
            lg[e0] = acc;
            lmax = fmaxf(lmax, acc);
        } else {
            lg[e0] = -1e30f;
        }
    }
    #pragma unroll
    for (int o = 16; o > 0; o >>= 1)
        lmax = fmaxf(lmax, __shfl_xor_sync(0xffffffffu, lmax, o));

    // pass 2: exp (independent) + weighted V accumulation
    float sum = 0.f;
    float oacc[HDd] = {0.f,0.f,0.f,0.f,0.f,0.f};
    #pragma unroll
    for (int e0 = 0; e0 < 20; e0++) {
        int e = lane + e0*32;
        if (e < KK*KK) {
            float pr = __expf(lg[e0] - lmax);
            sum += pr;
            int a = e / KK, c = e - a*KK;
            const float* vp = vs + (a*32 + colbase + c)*PITCH + n*HDd;
            float2 v01 = *(const float2*)(vp);
            float2 v23 = *(const float2*)(vp + 2);
            float2 v45 = *(const float2*)(vp + 4);
            oacc[0] = fmaf(pr, v01.x, oacc[0]);
            oacc[1] = fmaf(pr, v01.y, oacc[1]);
            oacc[2] = fmaf(pr, v23.x, oacc[2]);
            oacc[3] = fmaf(pr, v23.y, oacc[3]);
            oacc[4] = fmaf(pr, v45.x, oacc[4]);
            oacc[5] = fmaf(pr, v45.y, oacc[5]);
        }
    }
    #pragma unroll
    for (int o = 16; o > 0; o >>= 1) {
        sum += __shfl_xor_sync(0xffffffffu, sum, o);
        #pragma unroll
        for (int d = 0; d < HDd; d++)
            oacc[d] += __shfl_xor_sync(0xffffffffu, oacc[d], o);
    }
    if (lane == 0) {
        float inv = 1.0f / sum;
        #pragma unroll
        for (int d = 0; d < HDd; d++) ao[p*NUc + n*HDd + d] = oacc[d]*inv;
    }
    __syncthreads();

    // output projection (24x24) -> po
    if (tid < 8*NUc) {
        int pp = tid / NUc, oc = tid % NUc;
        float acc = __ldg(pb + oc);
        const float* wrow = pw + oc*NUc;
        #pragma unroll
        for (int ic = 0; ic < NUc; ic++)
            acc = fmaf(ao[pp*NUc + ic], __ldg(wrow + ic), acc);
        po[pp*NUc + oc] = acc;
    }
    __syncthreads();

    if (mode == 0) {
        // fused QKV for layer 2: 8 px * 72 oc = 576 dots
        if (tid < 8*72) {
            int pp = tid / 72, oc = tid % 72;
            float acc = bsh[oc];
            const float* wrow = wsh + oc*NUc;
            const float* xr = po + pp*NUc;
            #pragma unroll
            for (int c = 0; c < NUc; c++) acc = fmaf(xr[c], wrow[c], acc);
            int e = oc / NUc, ch = oc % NUc;
            int gpx = i*WW + j0 + pp;
            if      (e == 0) g_q1[gpx*NUc + ch] = acc * QSCALE;
            else if (e == 1) g_k1[gpx*NUc + ch] = acc;
            else             g_v1[gpx*NUc + ch] = acc;
        }
    } else {
        // final head (24 -> 5)
        if (tid < 8*5) {
            int pp = tid / 5, r = tid % 5;
            float acc = __ldg(ob + r);
            const float* wrow = ow + r*NUc;
            #pragma unroll
            for (int ic = 0; ic < NUc; ic++)
                acc = fmaf(po[pp*NUc + ic], __ldg(wrow + ic), acc);
            out[(i*WW + j0 + pp)*5 + r] = acc;
        }
    }
}

// ---------------------------------------------------------------------------
extern "C" void kernel_launch(void* const* d_in, const int* in_sizes, int n_in,
                              void* d_out, int out_size)
{
    const float* features  = (const float*)d_in[0];
    const int*   condition = (const int*)  d_in[1];
    const float* mask      = (const float*)d_in[2];
    const float* emb       = (const float*)d_in[3];
    const float* wih0      = (const float*)d_in[4];
    const float* whh0      = (const float*)d_in[5];
    const float* bih0      = (const float*)d_in[6];
    const float* bhh0      = (const float*)d_in[7];
    const float* wih1      = (const float*)d_in[8];
    const float* whh1      = (const float*)d_in[9];
    const float* bih1      = (const float*)d_in[10];
    const float* bhh1      = (const float*)d_in[11];
    const float* qkv_w     = (const float*)d_in[12];
    const float* qkv_b     = (const float*)d_in[13];
    const float* rpb       = (const float*)d_in[14];
    const float* proj_w    = (const float*)d_in[15];
    const float* proj_b    = (const float*)d_in[16];
    const float* out_w     = (const float*)d_in[17];
    const float* out_b     = (const float*)d_in[18];
    float* out = (float*)d_out;

    float *pq0, *pk0, *pv0, *pq1, *pk1, *pv1;
    cudaGetSymbolAddress((void**)&pq0, g_q0);
    cudaGetSymbolAddress((void**)&pk0, g_k0);
    cudaGetSymbolAddress((void**)&pv0, g_v0);
    cudaGetSymbolAddress((void**)&pq1, g_q1);
    cudaGetSymbolAddress((void**)&pk1, g_k1);
    cudaGetSymbolAddress((void**)&pv1, g_v1);

    const int natten_smem =
        (2*KK*32*PITCH + 2*8*NUc + 72*NUc + 72) * (int)sizeof(float); // ~175 KB
    cudaFuncSetAttribute(natten_kernel,
                         cudaFuncAttributeMaxDynamicSharedMemorySize, natten_smem);

    // 1) fused LSTM + QKV(layer1)
    lstm_kernel<<<WW, 96>>>(features, condition, mask, emb,
                            wih0, whh0, bih0, bhh0,
                            wih1, whh1, bih1, bhh1,
                            qkv_w, qkv_b);

    dim3 ngrid(WW/8, TT);

    // 2) NATTEN layer 1 (+ fused QKV for layer 2)
    natten_kernel<<<ngrid, 1024, natten_smem>>>(pq0, pk0, pv0,
                                                rpb, proj_w, proj_b,
                                                qkv_w, qkv_b, out_w, out_b,
                                                nullptr, 0);

    // 3) NATTEN layer 2 (+ fused head) -> d_out
    natten_kernel<<<ngrid, 1024, natten_smem>>>(pq1, pk1, pv1,
                                                rpb, proj_w, proj_b,
                                                qkv_w, qkv_b, out_w, out_b,
                                                out, 1);
}

// round 6
// speedup vs baseline: 1.6443x; 1.0437x over previous
#include <cuda_runtime.h>
#include <cuda_bf16.h>

// Problem constants
#define TT   64
#define WW   88
#define HPc  48
#define CIN  53
#define HLc  12
#define G4   48
#define NHh  4
#define HDd  6
#define NUc  24
#define KK   25
#define NPX  (TT*WW)   // 5632
#define PITCH 26       // float2-aligned; stride 13 float2 -> conflict-free

// Scratch buffers (device globals) — two full qkv sets (layer1 / layer2)
__device__ float g_q0[NPX*NUc];
__device__ float g_k0[NPX*NUc];
__device__ float g_v0[NPX*NUc];
__device__ float g_q1[NPX*NUc];
__device__ float g_k1[NPX*NUc];
__device__ float g_v1[NPX*NUc];

#define QSCALE 0.4082482904638631f

__device__ __forceinline__ float sigf(float x) {
    return __fdividef(1.0f, 1.0f + __expf(-x));
}
__device__ __forceinline__ float tanh_fast(float x) {
    return fmaf(2.0f, __fdividef(1.0f, 1.0f + __expf(-2.0f*x)), -1.0f);
}

// ---------------------------------------------------------------------------
// Fused: input build + 2 bidirectional LSTM layers + QKV for natten layer 1.
// Block per sequence (w), 384 threads:
//   pregates:   (t-chunk 0..3, gate 0..95) -> each thread does 16 timesteps
//   recurrence: warp0 = fwd, warp1 = bwd (shfl broadcast, no barriers)
//   qkv epi:    (t-chunk 0..3, oc 0..71)
// ---------------------------------------------------------------------------
__global__ void __launch_bounds__(384)
lstm_kernel(const float* __restrict__ features,
            const int*   __restrict__ condition,
            const float* __restrict__ mask,
            const float* __restrict__ emb,
            const float* __restrict__ wih0, const float* __restrict__ whh0,
            const float* __restrict__ bih0, const float* __restrict__ bhh0,
            const float* __restrict__ wih1, const float* __restrict__ whh1,
            const float* __restrict__ bih1, const float* __restrict__ bhh1,
            const float* __restrict__ qkv_w,  // (72,24)
            const float* __restrict__ qkv_b)  // (72,)
{
    const int w   = blockIdx.x;
    const int tid = threadIdx.x;

    __shared__ float xs  [TT][CIN];
    __shared__ float pre [TT][96];
    __shared__ float hbuf[TT][2*HLc];

    // ---- build input sequence ----
    for (int idx = tid; idx < TT*CIN; idx += 384) {
        int t = idx / CIN, c = idx % CIN;
        float val;
        if (c < HPc)            val = features[(t*HPc + c)*WW + w];
        else if (c < HPc + 4)   val = emb[condition[t*WW + w]*4 + (c - HPc)];
        else                    val = mask[t*WW + w];
        xs[t][c] = val;
    }
    __syncthreads();

    // ---- layer-0 pregates: 384 threads = 4 t-chunks x 96 gates ----
    {
        const int gate = tid % 96;          // varies within warp -> xs broadcast
        const int tq   = tid / 96;          // 0..3
        const int dir = gate / G4, g = gate % G4;
        float wr[CIN];
        const float* wrow = wih0 + (dir*G4 + g)*CIN;
        #pragma unroll
        for (int c = 0; c < CIN; c++) wr[c] = wrow[c];
        const float b = bih0[dir*G4 + g] + bhh0[dir*G4 + g];
        for (int t = tq*16; t < tq*16 + 16; t++) {
            float a0 = b, a1 = 0.f, a2 = 0.f, a3 = 0.f;
            #pragma unroll
            for (int c = 0; c < 52; c += 4) {
                a0 = fmaf(xs[t][c+0], wr[c+0], a0);
                a1 = fmaf(xs[t][c+1], wr[c+1], a1);
                a2 = fmaf(xs[t][c+2], wr[c+2], a2);
                a3 = fmaf(xs[t][c+3], wr[c+3], a3);
            }
            a0 = fmaf(xs[t][52], wr[52], a0);
            pre[t][gate] = (a0 + a1) + (a2 + a3);
        }
    }
    __syncthreads();

    // ---- layer-0 recurrence (2 warps, shfl, no barriers) ----
    if (tid < 64) {
        const int dir = tid >> 5, u = tid & 31;
        float wi[HLc], wf[HLc], wg[HLc], wo[HLc];
        if (u < HLc) {
            #pragma unroll
            for (int c = 0; c < HLc; c++) {
                wi[c] = whh0[(dir*G4      + u)*HLc + c];
                wf[c] = whh0[(dir*G4 + 12 + u)*HLc + c];
                wg[c] = whh0[(dir*G4 + 24 + u)*HLc + c];
                wo[c] = whh0[(dir*G4 + 36 + u)*HLc + c];
            }
        } else {
            #pragma unroll
            for (int c = 0; c < HLc; c++) { wi[c]=wf[c]=wg[c]=wo[c]=0.f; }
        }
        float h = 0.f, cs = 0.f;
        for (int s = 0; s < TT; s++) {
            const int t = dir ? (TT - 1 - s) : s;
            float gi, gf, gg, go;
            if (u < HLc) {
                gi = pre[t][dir*G4      + u];
                gf = pre[t][dir*G4 + 12 + u];
                gg = pre[t][dir*G4 + 24 + u];
                go = pre[t][dir*G4 + 36 + u];
            } else { gi = gf = gg = go = 0.f; }
            #pragma unroll
            for (int c = 0; c < HLc; c++) {
                float hc = __shfl_sync(0xffffffffu, h, c);
                gi = fmaf(hc, wi[c], gi);
                gf = fmaf(hc, wf[c], gf);
                gg = fmaf(hc, wg[c], gg);
                go = fmaf(hc, wo[c], go);
            }
            cs = sigf(gf)*cs + sigf(gi)*tanh_fast(gg);
            h  = sigf(go)*tanh_fast(cs);
            if (u < HLc) hbuf[t][dir*HLc + u] = h;
        }
    }
    __syncthreads();

    // ---- layer-1 pregates ----
    {
        const int gate = tid % 96;
        const int tq   = tid / 96;
        const int dir = gate / G4, g = gate % G4;
        float wr[2*HLc];
        const float* wrow = wih1 + (dir*G4 + g)*(2*HLc);
        #pragma unroll
        for (int c = 0; c < 2*HLc; c++) wr[c] = wrow[c];
        const float b = bih1[dir*G4 + g] + bhh1[dir*G4 + g];
        for (int t = tq*16; t < tq*16 + 16; t++) {
            float a0 = b, a1 = 0.f, a2 = 0.f, a3 = 0.f;
            #pragma unroll
            for (int c = 0; c < 2*HLc; c += 4) {
                a0 = fmaf(hbuf[t][c+0], wr[c+0], a0);
                a1 = fmaf(hbuf[t][c+1], wr[c+1], a1);
                a2 = fmaf(hbuf[t][c+2], wr[c+2], a2);
                a3 = fmaf(hbuf[t][c+3], wr[c+3], a3);
            }
            pre[t][gate] = (a0 + a1) + (a2 + a3);
        }
    }
    __syncthreads();

    // ---- layer-1 recurrence (writes hbuf; pregates already consumed it) ----
    if (tid < 64) {
        const int dir = tid >> 5, u = tid & 31;
        float wi[HLc], wf[HLc], wg[HLc], wo[HLc];
        if (u < HLc) {
            #pragma unroll
            for (int c = 0; c < HLc; c++) {
                wi[c] = whh1[(dir*G4      + u)*HLc + c];
                wf[c] = whh1[(dir*G4 + 12 + u)*HLc + c];
                wg[c] = whh1[(dir*G4 + 24 + u)*HLc + c];
                wo[c] = whh1[(dir*G4 + 36 + u)*HLc + c];
            }
        } else {
            #pragma unroll
            for (int c = 0; c < HLc; c++) { wi[c]=wf[c]=wg[c]=wo[c]=0.f; }
        }
        float h = 0.f, cs = 0.f;
        for (int s = 0; s < TT; s++) {
            const int t = dir ? (TT - 1 - s) : s;
            float gi, gf, gg, go;
            if (u < HLc) {
                gi = pre[t][dir*G4      + u];
                gf = pre[t][dir*G4 + 12 + u];
                gg = pre[t][dir*G4 + 24 + u];
                go = pre[t][dir*G4 + 36 + u];
            } else { gi = gf = gg = go = 0.f; }
            #pragma unroll
            for (int c = 0; c < HLc; c++) {
                float hc = __shfl_sync(0xffffffffu, h, c);
                gi = fmaf(hc, wi[c], gi);
                gf = fmaf(hc, wf[c], gf);
                gg = fmaf(hc, wg[c], gg);
                go = fmaf(hc, wo[c], go);
            }
            cs = sigf(gf)*cs + sigf(gi)*tanh_fast(gg);
            h  = sigf(go)*tanh_fast(cs);
            if (u < HLc) hbuf[t][dir*HLc + u] = h;
        }
    }
    __syncthreads();

    // ---- fused QKV for layer 1: (t-chunk 0..3, oc 0..71) = 288 threads ----
    if (tid < 288) {
        const int oc = tid % 72;
        const int tq = tid / 72;
        float wr[NUc];
        const float* wrow = qkv_w + oc*NUc;
        #pragma unroll
        for (int c = 0; c < NUc; c++) wr[c] = wrow[c];
        const float b = qkv_b[oc];
        const int e  = oc / NUc;
        const int ch = oc % NUc;
        const float scale = (e == 0) ? QSCALE : 1.0f;
        float* dst = (e == 0) ? g_q0 : (e == 1) ? g_k0 : g_v0;
        for (int t = tq*16; t < tq*16 + 16; t++) {
            float a0 = b, a1 = 0.f, a2 = 0.f, a3 = 0.f;
            #pragma unroll
            for (int c = 0; c < NUc; c += 4) {
                a0 = fmaf(hbuf[t][c+0], wr[c+0], a0);
                a1 = fmaf(hbuf[t][c+1], wr[c+1], a1);
                a2 = fmaf(hbuf[t][c+2], wr[c+2], a2);
                a3 = fmaf(hbuf[t][c+3], wr[c+3], a3);
            }
            dst[(t*WW + w)*NUc + ch] = ((a0 + a1) + (a2 + a3)) * scale;
        }
    }
}

// ---------------------------------------------------------------------------
// NATTEN-2D: SINGLE pass, unshifted softmax (logits provably < ~60 so exp
// cannot overflow fp32). Fused proj; mode0 -> QKV for layer 2, mode1 -> head.
// ---------------------------------------------------------------------------
__global__ void __launch_bounds__(1024)
natten_kernel(const float* __restrict__ qsrc,
              const float* __restrict__ ksrc,
              const float* __restrict__ vsrc,
              const float* __restrict__ rpb,    // (4,49,49)
              const float* __restrict__ pw,     // (24,24)
              const float* __restrict__ pb,     // (24,)
              const float* __restrict__ qkv_w,  // (72,24)   mode 0
              const float* __restrict__ qkv_b,  // (72,)     mode 0
              const float* __restrict__ ow,     // (5,24)    mode 1
              const float* __restrict__ ob,     // (5,)      mode 1
              float* __restrict__ out,          // mode1: (64,88,5)
              int mode)
{
    const int i  = blockIdx.y;
    const int j0 = blockIdx.x * 8;
    extern __shared__ float sm[];
    float* ks  = sm;                          // [25*32][PITCH]
    float* vs  = ks + KK*32*PITCH;
    float* ao  = vs + KK*32*PITCH;            // [8][24]
    float* po  = ao + 8*NUc;                  // [8][24]
    float* wsh = po + 8*NUc;                  // [72*24]
    float* bsh = wsh + 72*NUc;                // [72]

    const int si      = min(max(i  - 12, 0), TT - KK);
    const int sj_min  = min(max(j0 - 12, 0), WW - KK);
    const int sj_last = min(max(j0 + 7 - 12, 0), WW - KK);
    const int ncols   = sj_last + KK - sj_min;                 // <= 32

    const int tid = threadIdx.x;

    if (mode == 0) {
        for (int x = tid; x < 72*NUc; x += 1024) wsh[x] = qkv_w[x];
        if (tid < 72) bsh[tid] = qkv_b[tid];
    }

    // stage K/V window
    const int npx = KK * ncols;
    for (int spx = tid; spx < npx; spx += 1024) {
        int a = spx / ncols, c = spx - a*ncols;
        int gpx = (si + a)*WW + (sj_min + c);
        float* kdst = ks + (a*32 + c)*PITCH;
        float* vdst = vs + (a*32 + c)*PITCH;
        const float4* kp = (const float4*)(ksrc + gpx*NUc);
        const float4* vp = (const float4*)(vsrc + gpx*NUc);
        #pragma unroll
        for (int f = 0; f < 6; f++) {
            float4 kd = kp[f];
            *(float2*)(kdst + f*4)     = make_float2(kd.x, kd.y);
            *(float2*)(kdst + f*4 + 2) = make_float2(kd.z, kd.w);
        }
        #pragma unroll
        for (int f = 0; f < 6; f++) {
            float4 vd = vp[f];
            *(float2*)(vdst + f*4)     = make_float2(vd.x, vd.y);
            *(float2*)(vdst + f*4 + 2) = make_float2(vd.z, vd.w);
        }
    }
    __syncthreads();

    const int warp = tid >> 5, lane = tid & 31;
    const int p = warp >> 2;
    const int n = warp & 3;
    const int j = j0 + p;
    const int sj = min(max(j - 12, 0), WW - KK);
    const int colbase = sj - sj_min;
    const int ra0 = si - i + (KK - 1);
    const int rc0 = sj - j + (KK - 1);
    const float* rp = rpb + n*49*49;

    float qr[HDd];
    {
        const float* qp = qsrc + ((i*WW + j)*NUc + n*HDd);
        #pragma unroll
        for (int d = 0; d < HDd; d++) qr[d] = qp[d];
    }

    // single pass: logit -> exp (no max shift) -> accumulate
    float sum = 0.f;
    float oacc[HDd] = {0.f,0.f,0.f,0.f,0.f,0.f};
    #pragma unroll
    for (int e0 = 0; e0 < 20; e0++) {
        int e = lane + e0*32;
        if (e < KK*KK) {
            int a = e / KK, c = e - a*KK;
            const int base = (a*32 + colbase + c)*PITCH + n*HDd;
            const float* kp = ks + base;
            float2 k01 = *(const float2*)(kp);
            float2 k23 = *(const float2*)(kp + 2);
            float2 k45 = *(const float2*)(kp + 4);
            float lg = __ldg(rp + (ra0 + a)*49 + (rc0 + c));
            lg = fmaf(qr[0], k01.x, lg);
            lg = fmaf(qr[1], k01.y, lg);
            lg = fmaf(qr[2], k23.x, lg);
            lg = fmaf(qr[3], k23.y, lg);
            lg = fmaf(qr[4], k45.x, lg);
            lg = fmaf(qr[5], k45.y, lg);
            float pr = __expf(lg);
            sum += pr;
            const float* vp = vs + base;
            float2 v01 = *(const float2*)(vp);
            float2 v23 = *(const float2*)(vp + 2);
            float2 v45 = *(const float2*)(vp + 4);
            oacc[0] = fmaf(pr, v01.x, oacc[0]);
            oacc[1] = fmaf(pr, v01.y, oacc[1]);
            oacc[2] = fmaf(pr, v23.x, oacc[2]);
            oacc[3] = fmaf(pr, v23.y, oacc[3]);
            oacc[4] = fmaf(pr, v45.x, oacc[4]);
            oacc[5] = fmaf(pr, v45.y, oacc[5]);
        }
    }
    #pragma unroll
    for (int o = 16; o > 0; o >>= 1) {
        sum += __shfl_xor_sync(0xffffffffu, sum, o);
        #pragma unroll
        for (int d = 0; d < HDd; d++)
            oacc[d] += __shfl_xor_sync(0xffffffffu, oacc[d], o);
    }
    if (lane == 0) {
        float inv = 1.0f / sum;
        #pragma unroll
        for (int d = 0; d < HDd; d++) ao[p*NUc + n*HDd + d] = oacc[d]*inv;
    }
    __syncthreads();

    // output projection (24x24) -> po
    if (tid < 8*NUc) {
        int pp = tid / NUc, oc = tid % NUc;
        float acc = __ldg(pb + oc);
        const float* wrow = pw + oc*NUc;
        #pragma unroll
        for (int ic = 0; ic < NUc; ic++)
            acc = fmaf(ao[pp*NUc + ic], __ldg(wrow + ic), acc);
        po[pp*NUc + oc] = acc;
    }
    __syncthreads();

    if (mode == 0) {
        // fused QKV for layer 2
        if (tid < 8*72) {
            int pp = tid / 72, oc = tid % 72;
            float acc = bsh[oc];
            const float* wrow = wsh + oc*NUc;
            const float* xr = po + pp*NUc;
            #pragma unroll
            for (int c = 0; c < NUc; c++) acc = fmaf(xr[c], wrow[c], acc);
            int e = oc / NUc, ch = oc % NUc;
            int gpx = i*WW + j0 + pp;
            if      (e == 0) g_q1[gpx*NUc + ch] = acc * QSCALE;
            else if (e == 1) g_k1[gpx*NUc + ch] = acc;
            else             g_v1[gpx*NUc + ch] = acc;
        }
    } else {
        // final head (24 -> 5)
        if (tid < 8*5) {
            int pp = tid / 5, r = tid % 5;
            float acc = __ldg(ob + r);
            const float* wrow = ow + r*NUc;
            #pragma unroll
            for (int ic = 0; ic < NUc; ic++)
                acc = fmaf(po[pp*NUc + ic], __ldg(wrow + ic), acc);
            out[(i*WW + j0 + pp)*5 + r] = acc;
        }
    }
}

// ---------------------------------------------------------------------------
extern "C" void kernel_launch(void* const* d_in, const int* in_sizes, int n_in,
                              void* d_out, int out_size)
{
    const float* features  = (const float*)d_in[0];
    const int*   condition = (const int*)  d_in[1];
    const float* mask      = (const float*)d_in[2];
    const float* emb       = (const float*)d_in[3];
    const float* wih0      = (const float*)d_in[4];
    const float* whh0      = (const float*)d_in[5];
    const float* bih0      = (const float*)d_in[6];
    const float* bhh0      = (const float*)d_in[7];
    const float* wih1      = (const float*)d_in[8];
    const float* whh1      = (const float*)d_in[9];
    const float* bih1      = (const float*)d_in[10];
    const float* bhh1      = (const float*)d_in[11];
    const float* qkv_w     = (const float*)d_in[12];
    const float* qkv_b     = (const float*)d_in[13];
    const float* rpb       = (const float*)d_in[14];
    const float* proj_w    = (const float*)d_in[15];
    const float* proj_b    = (const float*)d_in[16];
    const float* out_w     = (const float*)d_in[17];
    const float* out_b     = (const float*)d_in[18];
    float* out = (float*)d_out;

    float *pq0, *pk0, *pv0, *pq1, *pk1, *pv1;
    cudaGetSymbolAddress((void**)&pq0, g_q0);
    cudaGetSymbolAddress((void**)&pk0, g_k0);
    cudaGetSymbolAddress((void**)&pv0, g_v0);
    cudaGetSymbolAddress((void**)&pq1, g_q1);
    cudaGetSymbolAddress((void**)&pk1, g_k1);
    cudaGetSymbolAddress((void**)&pv1, g_v1);

    const int natten_smem =
        (2*KK*32*PITCH + 2*8*NUc + 72*NUc + 72) * (int)sizeof(float); // ~175 KB
    cudaFuncSetAttribute(natten_kernel,
                         cudaFuncAttributeMaxDynamicSharedMemorySize, natten_smem);

    // 1) fused LSTM + QKV(layer1)
    lstm_kernel<<<WW, 384>>>(features, condition, mask, emb,
                             wih0, whh0, bih0, bhh0,
                             wih1, whh1, bih1, bhh1,
                             qkv_w, qkv_b);

    dim3 ngrid(WW/8, TT);

    // 2) NATTEN layer 1 (+ fused QKV for layer 2)
    natten_kernel<<<ngrid, 1024, natten_smem>>>(pq0, pk0, pv0,
                                                rpb, proj_w, proj_b,
                                                qkv_w, qkv_b, out_w, out_b,
                                                nullptr, 0);

    // 3) NATTEN layer 2 (+ fused head) -> d_out
    natten_kernel<<<ngrid, 1024, natten_smem>>>(pq1, pk1, pv1,
                                                rpb, proj_w, proj_b,
                                                qkv_w, qkv_b, out_w, out_b,
                                                out, 1);
}